// round 3
// baseline (speedup 1.0000x reference)
#include <cuda_runtime.h>
#include <math.h>

// Problem constants
#define B_  64
#define T_  10
#define D_  1024
#define E_  2048
#define M_  640            // B*T
#define SCALE_ 0.022097086912079612f   // 1/sqrt(2048)

typedef unsigned long long u64;

// ---------------------------------------------------------------------------
// Scratch (device globals — no allocation allowed)
// ---------------------------------------------------------------------------
__device__ __align__(16) float g_joint[M_ * E_];            // [B,T,E]
__device__ __align__(16) float g_keyT[2][B_ * D_ * 12];     // [br][b][d][t(pad12)]
__device__ __align__(16) float g_valT[2][B_ * D_ * 12];     // [br][b][d][t(pad12)]
__device__ __align__(16) float g_att[2][M_ * E_];           // relu(tanh(weighted)) [br][B,T,E]

__device__ __forceinline__ float tanh_fast(float x) {
    float y;
    asm("tanh.approx.f32 %0, %1;" : "=f"(y) : "f"(x));
    return y;
}
__device__ __forceinline__ u64 pack2(float lo, float hi) {
    u64 r; asm("mov.b64 %0, {%1, %2};" : "=l"(r) : "f"(lo), "f"(hi)); return r;
}
__device__ __forceinline__ void unpack2(u64 v, float& lo, float& hi) {
    asm("mov.b64 {%0, %1}, %2;" : "=f"(lo), "=f"(hi) : "l"(v));
}
__device__ __forceinline__ u64 fma2(u64 a, u64 b, u64 c) {
    u64 d; asm("fma.rn.f32x2 %0, %1, %2, %3;" : "=l"(d) : "l"(a), "l"(b), "l"(c)); return d;
}
__device__ __forceinline__ u64 mul2(u64 a, u64 b) {
    u64 d; asm("mul.rn.f32x2 %0, %1, %2;" : "=l"(d) : "l"(a), "l"(b)); return d;
}

// ---------------------------------------------------------------------------
// joint = concat(audio, video) @ Wq + bq        [640,2048] x [2048,2048]
// 64x64 tile, BK=16, 256 threads, 4x4 per thread. A tile kept in smem as
// duplicated (a,a) u64 lanes; B pairs read directly as ulonglong2. Inner
// loop: 1 LDS.128 + 4 LDS.64 + 8 FFMA2 per k -> FMA-pipe bound.
// ---------------------------------------------------------------------------
__global__ __launch_bounds__(256) void k_joint(const float* __restrict__ audio,
                                               const float* __restrict__ video,
                                               const float* __restrict__ Wq,
                                               const float* __restrict__ bq) {
    __shared__ __align__(16) u64  sA[64][17];
    __shared__ __align__(16) float sB[16][68];
    const int bm = blockIdx.y * 64, bn = blockIdx.x * 64;
    const int tid = threadIdx.x;
    const int tx = tid & 15, ty = tid >> 4;

    u64 acc[4][2] = {};
    for (int k0 = 0; k0 < E_; k0 += 16) {
        const float* src = (k0 < D_) ? audio : video;
        const int kb = (k0 < D_) ? k0 : (k0 - D_);
        #pragma unroll
        for (int i = 0; i < 4; i++) {
            int idx = tid + i * 256;
            int r = idx >> 4, c = idx & 15;
            float v = src[(bm + r) * D_ + kb + c];
            sA[r][c] = pack2(v, v);
        }
        #pragma unroll
        for (int i = 0; i < 4; i++) {
            int idx = tid + i * 256;
            int r = idx >> 6, c = idx & 63;
            sB[r][c] = Wq[(k0 + r) * E_ + bn + c];
        }
        __syncthreads();
        #pragma unroll
        for (int k = 0; k < 16; k++) {
            ulonglong2 bp = *(const ulonglong2*)&sB[k][tx * 4];
            #pragma unroll
            for (int i = 0; i < 4; i++) {
                u64 ap = sA[ty * 4 + i][k];
                acc[i][0] = fma2(ap, bp.x, acc[i][0]);
                acc[i][1] = fma2(ap, bp.y, acc[i][1]);
            }
        }
        __syncthreads();
    }
    float4 bias = *(const float4*)&bq[bn + tx * 4];
    #pragma unroll
    for (int i = 0; i < 4; i++) {
        float4 o;
        unpack2(acc[i][0], o.x, o.y);
        unpack2(acc[i][1], o.z, o.w);
        o.x += bias.x; o.y += bias.y; o.z += bias.z; o.w += bias.w;
        *(float4*)&g_joint[(size_t)(bm + ty * 4 + i) * E_ + bn + tx * 4] = o;
    }
}

// ---------------------------------------------------------------------------
// key{1,2}[b,d,t] = sum_t' x[b,t',d] * Wk[t',t] + bk[t]   (tiny 10x10 linear)
// One thread per (b,d). Stored padded to stride 12 for float4 reads later.
// grid: (256, 2)  block: 256
// ---------------------------------------------------------------------------
__global__ __launch_bounds__(256) void k_key(const float* __restrict__ audio,
                                             const float* __restrict__ video,
                                             const float* __restrict__ Wk1,
                                             const float* __restrict__ bk1,
                                             const float* __restrict__ Wk2,
                                             const float* __restrict__ bk2) {
    const int br = blockIdx.y;
    const float* x  = br ? video : audio;
    const float* Wk = br ? Wk2 : Wk1;
    const float* bk = br ? bk2 : bk1;

    __shared__ float w[100];
    __shared__ float bkv[10];
    if (threadIdx.x < 100) w[threadIdx.x] = Wk[threadIdx.x];
    if (threadIdx.x < 10)  bkv[threadIdx.x] = bk[threadIdx.x];
    __syncthreads();

    const int idx = blockIdx.x * 256 + threadIdx.x;   // 0..65535
    const int b = idx >> 10, d = idx & 1023;

    float xr[10];
    #pragma unroll
    for (int t = 0; t < 10; t++) xr[t] = x[(b * T_ + t) * D_ + d];

    float* o = g_keyT[br] + (size_t)(b * D_ + d) * 12;
    #pragma unroll
    for (int t = 0; t < 10; t++) {
        float a = bkv[t];
        #pragma unroll
        for (int tp = 0; tp < 10; tp++) a = fmaf(xr[tp], w[tp * 10 + t], a);
        o[t] = a;
    }
    o[10] = 0.f; o[11] = 0.f;   // keep padding defined
}

// ---------------------------------------------------------------------------
// val = x @ Wv + bv   [640,1024] x [1024,1024]; stored TRANSPOSED as [b][d][t]
// grid: (16, 10, 2)  block: 256
// ---------------------------------------------------------------------------
__global__ __launch_bounds__(256) void k_val(const float* __restrict__ audio,
                                             const float* __restrict__ video,
                                             const float* __restrict__ Wv1,
                                             const float* __restrict__ bv1,
                                             const float* __restrict__ Wv2,
                                             const float* __restrict__ bv2) {
    const int br = blockIdx.z;
    const float* x  = br ? video : audio;
    const float* W  = br ? Wv2 : Wv1;
    const float* bv = br ? bv2 : bv1;

    __shared__ __align__(16) u64  sA[64][17];
    __shared__ __align__(16) float sB[16][68];
    const int bm = blockIdx.y * 64, bn = blockIdx.x * 64;
    const int tid = threadIdx.x;
    const int tx = tid & 15, ty = tid >> 4;

    u64 acc[4][2] = {};
    for (int k0 = 0; k0 < D_; k0 += 16) {
        #pragma unroll
        for (int i = 0; i < 4; i++) {
            int idx = tid + i * 256;
            int r = idx >> 4, c = idx & 15;
            float v = x[(bm + r) * D_ + k0 + c];
            sA[r][c] = pack2(v, v);
        }
        #pragma unroll
        for (int i = 0; i < 4; i++) {
            int idx = tid + i * 256;
            int r = idx >> 6, c = idx & 63;
            sB[r][c] = W[(k0 + r) * D_ + bn + c];
        }
        __syncthreads();
        #pragma unroll
        for (int k = 0; k < 16; k++) {
            ulonglong2 bp = *(const ulonglong2*)&sB[k][tx * 4];
            #pragma unroll
            for (int i = 0; i < 4; i++) {
                u64 ap = sA[ty * 4 + i][k];
                acc[i][0] = fma2(ap, bp.x, acc[i][0]);
                acc[i][1] = fma2(ap, bp.y, acc[i][1]);
            }
        }
        __syncthreads();
    }
    #pragma unroll
    for (int i = 0; i < 4; i++) {
        int m = bm + ty * 4 + i;
        int b = m / T_, t = m % T_;
        float c[4];
        unpack2(acc[i][0], c[0], c[1]);
        unpack2(acc[i][1], c[2], c[3]);
        #pragma unroll
        for (int j = 0; j < 4; j++) {
            int n = bn + tx * 4 + j;
            g_valT[br][(size_t)(b * D_ + n) * 12 + t] = c[j] + bv[n];
        }
    }
}

// ---------------------------------------------------------------------------
// Fused attention (no 537MB scores intermediate), f32x2-packed over e-pairs:
//   acc[t,e] = sum_d V[t,d] * tanh(SCALE * K[d,:] . J[:,e])
//   g_att[br][b,t,e] = relu(tanh(acc))
// Each thread owns 2 adjacent e columns. K/V held in shared duplicated as
// (k,k) 64-bit lanes so the inner loop is pure packed FMA + 2 MUFU per d.
// grid: (8 e-tiles, 64 b, 2 br)  block: 128
// ---------------------------------------------------------------------------
__global__ __launch_bounds__(128) void k_attn() {
    const int tid = threadIdx.x;
    const int e0  = blockIdx.x * 256 + tid * 2;
    const int b   = blockIdx.y;
    const int br  = blockIdx.z;

    __shared__ __align__(16) u64 sK[128][12];
    __shared__ __align__(16) u64 sV[128][12];

    const float* keyT = g_keyT[br] + (size_t)b * D_ * 12;
    const float* valT = g_valT[br] + (size_t)b * D_ * 12;
    const float* jp   = g_joint + (size_t)b * T_ * E_ + e0;

    u64 J[10], acc[10];
    #pragma unroll
    for (int t = 0; t < 10; t++) {
        float2 jv = *(const float2*)(jp + (size_t)t * E_);
        J[t]   = pack2(jv.x * SCALE_, jv.y * SCALE_);
        acc[t] = 0ull;
    }

    for (int d0 = 0; d0 < D_; d0 += 128) {
        __syncthreads();
        {
            const float4* kp = (const float4*)(keyT + (size_t)(d0 + tid) * 12);
            const float4* vp = (const float4*)(valT + (size_t)(d0 + tid) * 12);
            float4 ka = kp[0], kb4 = kp[1], kc = kp[2];
            float4 va = vp[0], vb4 = vp[1], vc = vp[2];
            u64* kd = sK[tid];
            u64* vd = sV[tid];
            kd[0] = pack2(ka.x, ka.x);  kd[1] = pack2(ka.y, ka.y);
            kd[2] = pack2(ka.z, ka.z);  kd[3] = pack2(ka.w, ka.w);
            kd[4] = pack2(kb4.x, kb4.x); kd[5] = pack2(kb4.y, kb4.y);
            kd[6] = pack2(kb4.z, kb4.z); kd[7] = pack2(kb4.w, kb4.w);
            kd[8] = pack2(kc.x, kc.x);  kd[9] = pack2(kc.y, kc.y);
            vd[0] = pack2(va.x, va.x);  vd[1] = pack2(va.y, va.y);
            vd[2] = pack2(va.z, va.z);  vd[3] = pack2(va.w, va.w);
            vd[4] = pack2(vb4.x, vb4.x); vd[5] = pack2(vb4.y, vb4.y);
            vd[6] = pack2(vb4.z, vb4.z); vd[7] = pack2(vb4.w, vb4.w);
            vd[8] = pack2(vc.x, vc.x);  vd[9] = pack2(vc.y, vc.y);
        }
        __syncthreads();

        #pragma unroll 4
        for (int dd = 0; dd < 128; dd++) {
            const ulonglong2* kr = (const ulonglong2*)sK[dd];
            ulonglong2 k01 = kr[0], k23 = kr[1], k45 = kr[2], k67 = kr[3], k89 = kr[4];
            u64 p = mul2(k01.x, J[0]);
            p = fma2(k01.y, J[1], p);
            p = fma2(k23.x, J[2], p);
            p = fma2(k23.y, J[3], p);
            p = fma2(k45.x, J[4], p);
            p = fma2(k45.y, J[5], p);
            p = fma2(k67.x, J[6], p);
            p = fma2(k67.y, J[7], p);
            p = fma2(k89.x, J[8], p);
            p = fma2(k89.y, J[9], p);
            float s0, s1;
            unpack2(p, s0, s1);
            u64 sp = pack2(tanh_fast(s0), tanh_fast(s1));
            const ulonglong2* vr = (const ulonglong2*)sV[dd];
            ulonglong2 v01 = vr[0], v23 = vr[1], v45 = vr[2], v67 = vr[3], v89 = vr[4];
            acc[0] = fma2(v01.x, sp, acc[0]);
            acc[1] = fma2(v01.y, sp, acc[1]);
            acc[2] = fma2(v23.x, sp, acc[2]);
            acc[3] = fma2(v23.y, sp, acc[3]);
            acc[4] = fma2(v45.x, sp, acc[4]);
            acc[5] = fma2(v45.y, sp, acc[5]);
            acc[6] = fma2(v67.x, sp, acc[6]);
            acc[7] = fma2(v67.y, sp, acc[7]);
            acc[8] = fma2(v89.x, sp, acc[8]);
            acc[9] = fma2(v89.y, sp, acc[9]);
        }
    }

    float* o = g_att[br] + (size_t)b * T_ * E_ + e0;
    #pragma unroll
    for (int t = 0; t < 10; t++) {
        float x0, x1;
        unpack2(acc[t], x0, x1);
        float2 r;
        r.x = fmaxf(tanhf(x0), 0.f);   // accurate tanh here (only 2.6M evals)
        r.y = fmaxf(tanhf(x1), 0.f);
        *(float2*)(o + (size_t)t * E_) = r;
    }
}

// ---------------------------------------------------------------------------
// Final fusion: out = audio + video + relu(att0 @ Wf + bf) + relu(att1 @ Wf + bf)
// Both branch GEMMs share W tiles. [640,2048] x [2048,1024], f32x2-packed,
// duplicated A tiles in smem. grid: (16, 10)  block: 256
// ---------------------------------------------------------------------------
__global__ __launch_bounds__(256) void k_fuse(const float* __restrict__ audio,
                                              const float* __restrict__ video,
                                              const float* __restrict__ Wf,
                                              const float* __restrict__ bf,
                                              float* __restrict__ out) {
    __shared__ __align__(16) u64  sA0[64][17];
    __shared__ __align__(16) u64  sA1[64][17];
    __shared__ __align__(16) float sB[16][68];
    const int bm = blockIdx.y * 64, bn = blockIdx.x * 64;
    const int tid = threadIdx.x;
    const int tx = tid & 15, ty = tid >> 4;

    u64 acc0[4][2] = {}, acc1[4][2] = {};
    for (int k0 = 0; k0 < E_; k0 += 16) {
        #pragma unroll
        for (int i = 0; i < 4; i++) {
            int idx = tid + i * 256;
            int r = idx >> 4, c = idx & 15;
            float a0 = g_att[0][(size_t)(bm + r) * E_ + k0 + c];
            float a1 = g_att[1][(size_t)(bm + r) * E_ + k0 + c];
            sA0[r][c] = pack2(a0, a0);
            sA1[r][c] = pack2(a1, a1);
        }
        #pragma unroll
        for (int i = 0; i < 4; i++) {
            int idx = tid + i * 256;
            int r = idx >> 6, c = idx & 63;
            sB[r][c] = Wf[(size_t)(k0 + r) * D_ + bn + c];
        }
        __syncthreads();
        #pragma unroll
        for (int k = 0; k < 16; k++) {
            ulonglong2 bp = *(const ulonglong2*)&sB[k][tx * 4];
            #pragma unroll
            for (int i = 0; i < 4; i++) {
                u64 a0 = sA0[ty * 4 + i][k];
                u64 a1 = sA1[ty * 4 + i][k];
                acc0[i][0] = fma2(a0, bp.x, acc0[i][0]);
                acc0[i][1] = fma2(a0, bp.y, acc0[i][1]);
                acc1[i][0] = fma2(a1, bp.x, acc1[i][0]);
                acc1[i][1] = fma2(a1, bp.y, acc1[i][1]);
            }
        }
        __syncthreads();
    }
    float4 bias = *(const float4*)&bf[bn + tx * 4];
    #pragma unroll
    for (int i = 0; i < 4; i++) {
        int m = bm + ty * 4 + i;
        float c0[4], c1[4];
        unpack2(acc0[i][0], c0[0], c0[1]);
        unpack2(acc0[i][1], c0[2], c0[3]);
        unpack2(acc1[i][0], c1[0], c1[1]);
        unpack2(acc1[i][1], c1[2], c1[3]);
        float4 av = *(const float4*)&audio[(size_t)m * D_ + bn + tx * 4];
        float4 vv = *(const float4*)&video[(size_t)m * D_ + bn + tx * 4];
        float4 o;
        o.x = av.x + vv.x + fmaxf(c0[0] + bias.x, 0.f) + fmaxf(c1[0] + bias.x, 0.f);
        o.y = av.y + vv.y + fmaxf(c0[1] + bias.y, 0.f) + fmaxf(c1[1] + bias.y, 0.f);
        o.z = av.z + vv.z + fmaxf(c0[2] + bias.z, 0.f) + fmaxf(c1[2] + bias.z, 0.f);
        o.w = av.w + vv.w + fmaxf(c0[3] + bias.w, 0.f) + fmaxf(c1[3] + bias.w, 0.f);
        *(float4*)&out[(size_t)m * D_ + bn + tx * 4] = o;
    }
}

// ---------------------------------------------------------------------------
// Launch
// ---------------------------------------------------------------------------
extern "C" void kernel_launch(void* const* d_in, const int* in_sizes, int n_in,
                              void* d_out, int out_size) {
    (void)in_sizes; (void)n_in; (void)out_size;
    const float* audio = (const float*)d_in[0];
    const float* video = (const float*)d_in[1];
    const float* Wq  = (const float*)d_in[2];
    const float* bq  = (const float*)d_in[3];
    const float* Wk1 = (const float*)d_in[4];
    const float* bk1 = (const float*)d_in[5];
    const float* Wk2 = (const float*)d_in[6];
    const float* bk2 = (const float*)d_in[7];
    const float* Wv1 = (const float*)d_in[8];
    const float* bv1 = (const float*)d_in[9];
    const float* Wv2 = (const float*)d_in[10];
    const float* bv2 = (const float*)d_in[11];
    const float* Wf  = (const float*)d_in[12];
    const float* bf  = (const float*)d_in[13];
    float* out = (float*)d_out;

    k_joint<<<dim3(32, 10), 256>>>(audio, video, Wq, bq);
    k_key<<<dim3(256, 2), 256>>>(audio, video, Wk1, bk1, Wk2, bk2);
    k_val<<<dim3(16, 10, 2), 256>>>(audio, video, Wv1, bv1, Wv2, bv2);
    k_attn<<<dim3(8, 64, 2), 128>>>();
    k_fuse<<<dim3(16, 10), 256>>>(audio, video, Wf, bf, out);
}